// round 16
// baseline (speedup 1.0000x reference)
#include <cuda_runtime.h>
#include <cstdint>
#include <cstddef>

namespace {
constexpr int kB = 16, kS = 2048, kD = 128, TQ = 128, TK = 128, NT = 512;
constexpr int NKT = kS / TK;   // 16
constexpr int PITCH = 132;     // all tiles: 132 % 32 == 4 -> ldmatrix conflict-free
constexpr float kC = 0.12752991043f;   // 1/sqrt(128) * log2(e)

struct Smem {
  float Qs[TQ * PITCH];                                      // 67.6 KB
  union { float Ks[TK * PITCH]; float VT[kD * PITCH]; } kv;  // 67.6 KB
  float Ps[TQ * PITCH];                                      // 67.6 KB
  float Zs[TQ];
  float rZs[TQ];
  float Zp[4][TQ];
  float Vps[4][kD];
  float Vcsum[kD];
};
constexpr int SMEM_BYTES = (int)sizeof(Smem);                // ~204 KB

__device__ __forceinline__ float exp_mufu(float s) {
  float y = s * kC, r;
  asm("ex2.approx.ftz.f32 %0, %1;" : "=f"(r) : "f"(y));
  return r;
}
__device__ __forceinline__ float exp_poly(float s) {
  float y = s * kC;
  float r = y + 12582912.0f;
  float f = y - (r - 12582912.0f);
  int n = __float_as_int(r);
  float p = 0.0096181f;
  p = fmaf(p, f, 0.0555042f);
  p = fmaf(p, f, 0.2402265f);
  p = fmaf(p, f, 0.6931472f);
  p = fmaf(p, f, 1.0f);
  return __int_as_float(__float_as_int(p) + (n << 23));
}
__device__ __forceinline__ uint32_t f2tf32(float f) {
  uint32_t u; asm("cvt.rna.tf32.f32 %0, %1;" : "=r"(u) : "f"(f)); return u;
}
__device__ __forceinline__ float tff(float f) { return __uint_as_float(f2tf32(f)); }

__device__ __forceinline__ void ldm_x4(uint32_t* r, uint32_t a) {
  asm volatile("ldmatrix.sync.aligned.m8n8.x4.shared.b16 {%0,%1,%2,%3}, [%4];"
               : "=r"(r[0]), "=r"(r[1]), "=r"(r[2]), "=r"(r[3]) : "r"(a));
}
__device__ __forceinline__ void mma_tf32(float c[4], const uint32_t a[4],
                                         uint32_t b0, uint32_t b1) {
  asm volatile(
      "mma.sync.aligned.m16n8k8.row.col.f32.tf32.tf32.f32 "
      "{%0,%1,%2,%3}, {%4,%5,%6,%7}, {%8,%9}, {%0,%1,%2,%3};\n"
      : "+f"(c[0]), "+f"(c[1]), "+f"(c[2]), "+f"(c[3])
      : "r"(a[0]), "r"(a[1]), "r"(a[2]), "r"(a[3]), "r"(b0), "r"(b1));
}
}  // namespace

extern "C" __global__ void __launch_bounds__(NT, 1)
sdpa_kernel(const float* __restrict__ Q, const float* __restrict__ K,
            const float* __restrict__ V, float* __restrict__ out,
            float* __restrict__ attn)
{
  extern __shared__ char smem_raw[];
  Smem& sm = *reinterpret_cast<Smem*>(smem_raw);

  const int qt  = blockIdx.x;
  const int b   = blockIdx.y;
  const int tid = threadIdx.x;
  const int q0  = qt * TQ;
  const int wid  = tid >> 5;        // 0..15
  const int lane = tid & 31;
  const int wr   = wid >> 2;        // 0..3 -> rows 32*wr
  const int wc   = wid & 3;         // 0..3 -> cols 32*wc
  const int gid  = lane >> 2;       // 0..7
  const int tig  = lane & 3;        // 0..3

  const float* Qb = Q + (size_t)b * kS * kD;
  const float* Kb = K + (size_t)b * kS * kD;
  const float* Vb = V + (size_t)b * kS * kD;
  float* outb  = out  + (size_t)b * kS * kD;
  float* attnb = attn + (size_t)b * kS * kS;

  const uint32_t smQ  = (uint32_t)__cvta_generic_to_shared(sm.Qs);
  const uint32_t smK  = (uint32_t)__cvta_generic_to_shared(sm.kv.Ks);
  const uint32_t smVT = (uint32_t)__cvta_generic_to_shared(sm.kv.VT);
  const uint32_t smP  = (uint32_t)__cvta_generic_to_shared(sm.Ps);

  // ldmatrix bases (patterns verified in R10); second address = +16 rows
  const uint32_t rowA = (uint32_t)(32 * wr + (lane & 15));
  const uint32_t qa0 = smQ + rowA * PITCH * 4 + (lane >> 4) * 16;
  const uint32_t qa1 = qa0 + 16 * PITCH * 4;
  const uint32_t pa0 = smP + rowA * PITCH * 4 + (lane >> 4) * 16;
  const uint32_t pa1 = pa0 + 16 * PITCH * 4;
  const uint32_t rowB = (uint32_t)(32 * wc + (lane & 7) + 8 * (lane >> 4));
  const uint32_t kb0 = smK + rowB * PITCH * 4 + ((lane >> 3) & 1) * 16;
  const uint32_t kb1 = kb0 + 16 * PITCH * 4;
  const uint32_t vb0 = smVT + rowB * PITCH * 4 + ((lane >> 3) & 1) * 16;
  const uint32_t vb1 = vb0 + 16 * PITCH * 4;

  // ---- stage Q (tf32, once): 128 rows x 32 float4 ----
  {
    const float4* Qg = reinterpret_cast<const float4*>(Qb + (size_t)q0 * kD);
#pragma unroll
    for (int j = 0; j < 8; ++j) {
      const int f = tid + j * NT;
      const int r = f >> 5, c4 = f & 31;
      float4 v = Qg[f];
      float4 t = make_float4(tff(v.x), tff(v.y), tff(v.z), tff(v.w));
      *reinterpret_cast<float4*>(&sm.Qs[r * PITCH + c4 * 4]) = t;
    }
  }
  if (tid < TQ) sm.Zs[tid] = (float)q0;

  // V staging ownership: d-col vd, tokens tok0..tok0+31
  const int vd   = tid & 127;
  const int tok0 = 32 * (tid >> 7);

  // prefetch first K tile
  float4 kreg[8];
  {
    const float4* Kg = reinterpret_cast<const float4*>(Kb + (size_t)qt * TK * kD);
#pragma unroll
    for (int j = 0; j < 8; ++j) kreg[j] = Kg[tid + j * NT];
  }

  float oacc[2][4][4];
#pragma unroll
  for (int mi = 0; mi < 2; ++mi)
#pragma unroll
    for (int nj = 0; nj < 4; ++nj)
#pragma unroll
      for (int v = 0; v < 4; ++v) oacc[mi][nj][v] = 0.f;

  // ================= Phase 1 =================
  for (int kt = qt; kt < NKT; ++kt) {
    const int k0 = kt * TK;
    __syncthreads();   // [0] prev PV reads of union/Ps done (Q ready on i=0)

    // stage K (tf32) into union
#pragma unroll
    for (int j = 0; j < 8; ++j) {
      const int f = tid + j * NT;
      const int r = f >> 5, c4 = f & 31;
      float4 t = make_float4(tff(kreg[j].x), tff(kreg[j].y),
                             tff(kreg[j].z), tff(kreg[j].w));
      *reinterpret_cast<float4*>(&sm.kv.Ks[r * PITCH + c4 * 4]) = t;
    }
    __syncthreads();   // [1] Ks visible

    // issue V loads for this tile (in flight during QK)
    float vreg[32];
    {
      const float* Vg = Vb + (size_t)k0 * kD;
#pragma unroll
      for (int i = 0; i < 32; ++i)
        vreg[i] = Vg[(size_t)(tok0 + i) * kD + vd];
    }

    // ---- QK^T: 32x32 warp tile, k=128 ----
    float sacc[2][4][4];
#pragma unroll
    for (int mi = 0; mi < 2; ++mi)
#pragma unroll
      for (int nj = 0; nj < 4; ++nj)
#pragma unroll
        for (int v = 0; v < 4; ++v) sacc[mi][nj][v] = 0.f;
#pragma unroll
    for (int s = 0; s < 16; ++s) {
      uint32_t a0[4], a1[4], bk0[4], bk1[4];
      ldm_x4(a0, qa0 + (uint32_t)(s * 32));
      ldm_x4(a1, qa1 + (uint32_t)(s * 32));
      ldm_x4(bk0, kb0 + (uint32_t)(s * 32));
      ldm_x4(bk1, kb1 + (uint32_t)(s * 32));
      mma_tf32(sacc[0][0], a0, bk0[0], bk0[1]);
      mma_tf32(sacc[0][1], a0, bk0[2], bk0[3]);
      mma_tf32(sacc[0][2], a0, bk1[0], bk1[1]);
      mma_tf32(sacc[0][3], a0, bk1[2], bk1[3]);
      mma_tf32(sacc[1][0], a1, bk0[0], bk0[1]);
      mma_tf32(sacc[1][1], a1, bk0[2], bk0[3]);
      mma_tf32(sacc[1][2], a1, bk1[0], bk1[1]);
      mma_tf32(sacc[1][3], a1, bk1[2], bk1[3]);
    }

    // ---- mask + exp; attn store; Ps store; Z partials ----
    const bool diag = (kt == qt);
    float rs[2][2] = {{0.f, 0.f}, {0.f, 0.f}};
#pragma unroll
    for (int mi = 0; mi < 2; ++mi) {
      const int R0 = 32 * wr + 16 * mi + gid, R1 = R0 + 8;
      const int rg0 = q0 + R0, rg1 = q0 + R1;
      float* arow0 = attnb + (size_t)rg0 * kS + k0;
      float* arow1 = attnb + (size_t)rg1 * kS + k0;
#pragma unroll
      for (int nj = 0; nj < 4; ++nj) {
        const int c = 32 * wc + 8 * nj + 2 * tig;
        const int cg = k0 + c;
        float x00, x01, x10, x11;
        if (nj == 3) {
          x00 = exp_poly(sacc[mi][nj][0]);
          x01 = exp_poly(sacc[mi][nj][1]);
          x10 = exp_poly(sacc[mi][nj][2]);
          x11 = exp_poly(sacc[mi][nj][3]);
        } else {
          x00 = exp_mufu(sacc[mi][nj][0]);
          x01 = exp_mufu(sacc[mi][nj][1]);
          x10 = exp_mufu(sacc[mi][nj][2]);
          x11 = exp_mufu(sacc[mi][nj][3]);
        }
        float e00, e01, e10, e11;
        if (diag) {
          e00 = (cg     > rg0) ? x00 : 1.0f;
          e01 = (cg + 1 > rg0) ? x01 : 1.0f;
          e10 = (cg     > rg1) ? x10 : 1.0f;
          e11 = (cg + 1 > rg1) ? x11 : 1.0f;
        } else {
          e00 = x00; e01 = x01; e10 = x10; e11 = x11;
        }
        rs[mi][0] += e00 + e01;
        rs[mi][1] += e10 + e11;
        *reinterpret_cast<float2*>(arow0 + c) = make_float2(e00, e01);
        *reinterpret_cast<float2*>(arow1 + c) = make_float2(e10, e11);
        *reinterpret_cast<float2*>(&sm.Ps[R0 * PITCH + c]) =
            make_float2(tff(e00), tff(e01));
        *reinterpret_cast<float2*>(&sm.Ps[R1 * PITCH + c]) =
            make_float2(tff(e10), tff(e11));
      }
    }
#pragma unroll
    for (int mi = 0; mi < 2; ++mi) {
      float a = rs[mi][0], bq = rs[mi][1];
      a  += __shfl_xor_sync(0xffffffffu, a, 1, 4);
      a  += __shfl_xor_sync(0xffffffffu, a, 2, 4);
      bq += __shfl_xor_sync(0xffffffffu, bq, 1, 4);
      bq += __shfl_xor_sync(0xffffffffu, bq, 2, 4);
      if (tig == 0) {
        const int R0 = 32 * wr + 16 * mi + gid;
        sm.Zp[wc][R0] = a;
        sm.Zp[wc][R0 + 8] = bq;
      }
    }
    __syncthreads();   // [2] QK reads of union done; Ps + Zp visible
    if (tid < TQ)
      sm.Zs[tid] += (sm.Zp[0][tid] + sm.Zp[1][tid]) +
                    (sm.Zp[2][tid] + sm.Zp[3][tid]);

    // stage V^T (tf32) into union
#pragma unroll
    for (int m = 0; m < 8; ++m) {
      float4 t = make_float4(tff(vreg[4 * m + 0]), tff(vreg[4 * m + 1]),
                             tff(vreg[4 * m + 2]), tff(vreg[4 * m + 3]));
      *reinterpret_cast<float4*>(&sm.kv.VT[vd * PITCH + tok0 + 4 * m]) = t;
    }
    // prefetch next K (covered by PV)
    if (kt + 1 < NKT) {
      const float4* Kg = reinterpret_cast<const float4*>(Kb + (size_t)(k0 + TK) * kD);
#pragma unroll
      for (int j = 0; j < 8; ++j) kreg[j] = Kg[tid + j * NT];
    }
    __syncthreads();   // [3] VT visible

    // ---- PV: 32 rows x 32 d-cols per warp, k=128 ----
#pragma unroll
    for (int kk = 0; kk < 16; ++kk) {
      uint32_t ap0[4], ap1[4], bv0[4], bv1[4];
      ldm_x4(ap0, pa0 + (uint32_t)(kk * 32));
      ldm_x4(ap1, pa1 + (uint32_t)(kk * 32));
      ldm_x4(bv0, vb0 + (uint32_t)(kk * 32));
      ldm_x4(bv1, vb1 + (uint32_t)(kk * 32));
      mma_tf32(oacc[0][0], ap0, bv0[0], bv0[1]);
      mma_tf32(oacc[0][1], ap0, bv0[2], bv0[3]);
      mma_tf32(oacc[0][2], ap0, bv1[0], bv1[1]);
      mma_tf32(oacc[0][3], ap0, bv1[2], bv1[3]);
      mma_tf32(oacc[1][0], ap1, bv0[0], bv0[1]);
      mma_tf32(oacc[1][1], ap1, bv0[2], bv0[3]);
      mma_tf32(oacc[1][2], ap1, bv1[0], bv1[1]);
      mma_tf32(oacc[1][3], ap1, bv1[2], bv1[3]);
    }
  }

  // ================= Phase 2 =================
  __syncthreads();
  if (tid < TQ) sm.rZs[tid] = 1.0f / sm.Zs[tid];
  __syncthreads();

  // lower-region V column sums (deterministic, 4-way MLP)
  {
    const int vc = tid & 127, vq = tid >> 7;
    float a0 = 0.f, a1 = 0.f, a2 = 0.f, a3 = 0.f;
    for (int t = vq; t < q0; t += 16) {
      a0 += Vb[(size_t)t * kD + vc];
      a1 += Vb[(size_t)(t + 4) * kD + vc];
      a2 += Vb[(size_t)(t + 8) * kD + vc];
      a3 += Vb[(size_t)(t + 12) * kD + vc];
    }
    sm.Vps[vq][vc] = (a0 + a1) + (a2 + a3);
  }

  // cache 1/Z for the 8 rows this thread touches in fill/rescale
  float rzr[8];
#pragma unroll
  for (int i = 0; i < 8; ++i) rzr[i] = sm.rZs[(tid >> 5) + 16 * i];

  // lower attn fill = 1/Z (128 rows x 32 float4 per 128-col tile)
  for (int kt = 0; kt < qt; ++kt) {
    const int k0 = kt * TK;
#pragma unroll
    for (int i = 0; i < 8; ++i) {
      const int idx = tid + i * NT;
      const int r = idx >> 5, c4 = idx & 31;
      const float rz = rzr[i];
      *reinterpret_cast<float4*>(&attnb[(size_t)(q0 + r) * kS + k0 + 4 * c4]) =
          make_float4(rz, rz, rz, rz);
    }
  }
  __syncthreads();
  if (tid < kD)
    sm.Vcsum[tid] = (sm.Vps[0][tid] + sm.Vps[1][tid]) +
                    (sm.Vps[2][tid] + sm.Vps[3][tid]);
  __syncthreads();

  // rescale upper attn tiles: attn *= 1/Z
  for (int kt = qt; kt < NKT; ++kt) {
    const int k0 = kt * TK;
#pragma unroll
    for (int i = 0; i < 8; ++i) {
      const int idx = tid + i * NT;
      const int r = idx >> 5, c4 = idx & 31;
      float4* p = reinterpret_cast<float4*>(
          &attnb[(size_t)(q0 + r) * kS + k0 + 4 * c4]);
      float4 v = *p;
      const float rz = rzr[i];
      v.x *= rz; v.y *= rz; v.z *= rz; v.w *= rz;
      *p = v;
    }
  }

  // final output
#pragma unroll
  for (int mi = 0; mi < 2; ++mi) {
    const int R0 = 32 * wr + 16 * mi + gid, R1 = R0 + 8;
    const float rz0 = sm.rZs[R0], rz1 = sm.rZs[R1];
#pragma unroll
    for (int nj = 0; nj < 4; ++nj) {
      const int c = 32 * wc + 8 * nj + 2 * tig;
      const float vs0 = sm.Vcsum[c], vs1 = sm.Vcsum[c + 1];
      float2 o0 = make_float2(rz0 * (oacc[mi][nj][0] + vs0),
                              rz0 * (oacc[mi][nj][1] + vs1));
      float2 o1 = make_float2(rz1 * (oacc[mi][nj][2] + vs0),
                              rz1 * (oacc[mi][nj][3] + vs1));
      *reinterpret_cast<float2*>(&outb[(size_t)(q0 + R0) * kD + c]) = o0;
      *reinterpret_cast<float2*>(&outb[(size_t)(q0 + R1) * kD + c]) = o1;
    }
  }
}

extern "C" void kernel_launch(void* const* d_in, const int* in_sizes, int n_in,
                              void* d_out, int out_size) {
  (void)in_sizes; (void)n_in; (void)out_size;
  const float* Q = (const float*)d_in[0];
  const float* K = (const float*)d_in[1];
  const float* V = (const float*)d_in[2];
  float* out  = (float*)d_out;
  float* attn = out + (size_t)kB * kS * kD;

  cudaFuncSetAttribute(sdpa_kernel, cudaFuncAttributeMaxDynamicSharedMemorySize,
                       SMEM_BYTES);
  dim3 grid(kS / TQ, kB);   // heavy q-tiles first
  sdpa_kernel<<<grid, NT, SMEM_BYTES>>>(Q, K, V, out, attn);
}

// round 17
// speedup vs baseline: 1.6179x; 1.6179x over previous
#include <cuda_runtime.h>
#include <cuda_fp16.h>
#include <cstdint>
#include <cstddef>

namespace {
constexpr int kB = 16, kS = 2048, kD = 128, TQ = 64, TK = 64, NT = 512;
constexpr int NKT = kS / TK;   // 32
constexpr int QP = 136;        // Q/K pitch in halves: 272B = 17 groups == 1 mod 8
constexpr int VTP = 72;        // VT/Ps pitch in halves: 144B = 9 groups == 1 mod 8
constexpr int PP = 72;
constexpr float kC = 0.12752991043f;   // 1/sqrt(128) * log2(e)

struct Smem {
  __half Qs[TQ * QP];        // 17.4 KB
  __half Ks[TK * QP];        // 17.4 KB
  __half VT[kD * VTP];       // 18.4 KB  (transposed [d][tok])
  __half Ps[TQ * PP];        // 9.2 KB
  float Zs[TQ];
  float rZs[TQ];
  float Zp[4][TQ];
  float Vps[4][kD];
  float Vcsum[kD];
};
constexpr int SMEM_BYTES = (int)sizeof(Smem);   // ~67 KB

__device__ __forceinline__ float exp_mufu(float s) {
  float y = s * kC, r;
  asm("ex2.approx.ftz.f32 %0, %1;" : "=f"(r) : "f"(y));
  return r;
}
__device__ __forceinline__ float exp_poly(float s) {
  float y = s * kC;
  float r = y + 12582912.0f;
  float f = y - (r - 12582912.0f);
  int n = __float_as_int(r);
  float p = 0.0096181f;
  p = fmaf(p, f, 0.0555042f);
  p = fmaf(p, f, 0.2402265f);
  p = fmaf(p, f, 0.6931472f);
  p = fmaf(p, f, 1.0f);
  return __int_as_float(__float_as_int(p) + (n << 23));
}
__device__ __forceinline__ uint32_t h2pack(float lo, float hi) {
  __half2 h = __floats2half2_rn(lo, hi);
  return *reinterpret_cast<uint32_t*>(&h);
}
__device__ __forceinline__ void ldm_x4(uint32_t* r, uint32_t a) {
  asm volatile("ldmatrix.sync.aligned.m8n8.x4.shared.b16 {%0,%1,%2,%3}, [%4];"
               : "=r"(r[0]), "=r"(r[1]), "=r"(r[2]), "=r"(r[3]) : "r"(a));
}
__device__ __forceinline__ void mma_f16(float c[4], const uint32_t a[4],
                                        uint32_t b0, uint32_t b1) {
  asm volatile(
      "mma.sync.aligned.m16n8k16.row.col.f32.f16.f16.f32 "
      "{%0,%1,%2,%3}, {%4,%5,%6,%7}, {%8,%9}, {%0,%1,%2,%3};\n"
      : "+f"(c[0]), "+f"(c[1]), "+f"(c[2]), "+f"(c[3])
      : "r"(a[0]), "r"(a[1]), "r"(a[2]), "r"(a[3]), "r"(b0), "r"(b1));
}
}  // namespace

extern "C" __global__ void __launch_bounds__(NT, 1)
sdpa_kernel(const float* __restrict__ Q, const float* __restrict__ K,
            const float* __restrict__ V, float* __restrict__ out,
            float* __restrict__ attn)
{
  extern __shared__ char smem_raw[];
  Smem& sm = *reinterpret_cast<Smem*>(smem_raw);

  const int qt  = blockIdx.x;
  const int b   = blockIdx.y;
  const int tid = threadIdx.x;
  const int q0  = qt * TQ;
  const int wid  = tid >> 5;        // 0..15
  const int lane = tid & 31;
  const int wr   = wid >> 2;        // 0..3  rows 16*wr
  const int wc   = wid & 3;         // 0..3  QK cols 16*wc / PV d-cols 32*wc
  const int gid  = lane >> 2;
  const int tig  = lane & 3;
  const int r0 = 16 * wr + gid, r1 = r0 + 8;

  const float* Qb = Q + (size_t)b * kS * kD;
  const float* Kb = K + (size_t)b * kS * kD;
  const float* Vb = V + (size_t)b * kS * kD;
  float* outb  = out  + (size_t)b * kS * kD;
  float* attnb = attn + (size_t)b * kS * kS;

  char* smQ  = reinterpret_cast<char*>(sm.Qs);
  char* smK  = reinterpret_cast<char*>(sm.Ks);
  char* smVT = reinterpret_cast<char*>(sm.VT);
  char* smP  = reinterpret_cast<char*>(sm.Ps);
  const uint32_t uQ  = (uint32_t)__cvta_generic_to_shared(smQ);
  const uint32_t uK  = (uint32_t)__cvta_generic_to_shared(smK);
  const uint32_t uVT = (uint32_t)__cvta_generic_to_shared(smVT);
  const uint32_t uP  = (uint32_t)__cvta_generic_to_shared(smP);

  // ldmatrix base addresses (A: 16-row x k16 blocks; B: two n/d octets x k16)
  const uint32_t qa = uQ + (uint32_t)((16 * wr + (lane & 15)) * QP * 2 + (lane >> 4) * 16);
  const uint32_t pa = uP + (uint32_t)((16 * wr + (lane & 15)) * PP * 2 + (lane >> 4) * 16);
  const uint32_t kb = uK + (uint32_t)((16 * wc + (lane & 7) + 8 * (lane >> 4)) * QP * 2 +
                                      ((lane >> 3) & 1) * 16);
  const uint32_t vb0 = uVT + (uint32_t)((32 * wc + (lane & 7) + 8 * (lane >> 4)) * VTP * 2 +
                                        ((lane >> 3) & 1) * 16);
  const uint32_t vb1 = vb0 + (uint32_t)(16 * VTP * 2);

  // ---- stage Q (fp16, once): 4 float4 loads -> 2 half2-pairs each ----
  {
    const float4* Qg = reinterpret_cast<const float4*>(Qb + (size_t)q0 * kD);
#pragma unroll
    for (int j = 0; j < 4; ++j) {
      const int f = tid + j * NT;
      const int r = f >> 5, c4 = f & 31;
      float4 v = Qg[f];
      uint2 t = make_uint2(h2pack(v.x, v.y), h2pack(v.z, v.w));
      *reinterpret_cast<uint2*>(smQ + r * (QP * 2) + c4 * 8) = t;
    }
  }
  if (tid < TQ) sm.Zs[tid] = (float)q0;

  // ---- prefetch first K/V tile ----
  float4 kreg[4];
  float vreg[16];
  const int vd  = 32 * (wid & 3) + lane;   // d column
  const int vt0 = 4 * (wid >> 2);          // token base
  {
    const float4* Kg = reinterpret_cast<const float4*>(Kb + (size_t)qt * TK * kD);
#pragma unroll
    for (int j = 0; j < 4; ++j) kreg[j] = Kg[tid + j * NT];
    const float* Vg = Vb + (size_t)qt * TK * kD;
#pragma unroll
    for (int j = 0; j < 4; ++j)
#pragma unroll
      for (int t = 0; t < 4; ++t)
        vreg[4 * j + t] = Vg[(size_t)(vt0 + 16 * j + t) * kD + vd];
  }

  float oacc[4][4];
#pragma unroll
  for (int j = 0; j < 4; ++j)
#pragma unroll
    for (int v = 0; v < 4; ++v) oacc[j][v] = 0.f;

  // ================= Phase 1 =================
  for (int kt = qt; kt < NKT; ++kt) {
    const int k0 = kt * TK;
    __syncthreads();

    // stage K (fp16)
#pragma unroll
    for (int j = 0; j < 4; ++j) {
      const int f = tid + j * NT;
      const int r = f >> 5, c4 = f & 31;
      uint2 t = make_uint2(h2pack(kreg[j].x, kreg[j].y),
                           h2pack(kreg[j].z, kreg[j].w));
      *reinterpret_cast<uint2*>(smK + r * (QP * 2) + c4 * 8) = t;
    }
    // stage V transposed (fp16): VT[d][tok]
#pragma unroll
    for (int j = 0; j < 4; ++j) {
      uint2 t = make_uint2(h2pack(vreg[4 * j + 0], vreg[4 * j + 1]),
                           h2pack(vreg[4 * j + 2], vreg[4 * j + 3]));
      *reinterpret_cast<uint2*>(smVT + vd * (VTP * 2) + (vt0 + 16 * j) * 2) = t;
    }
    // prefetch next tile
    if (kt + 1 < NKT) {
      const float4* Kg = reinterpret_cast<const float4*>(Kb + (size_t)(k0 + TK) * kD);
#pragma unroll
      for (int j = 0; j < 4; ++j) kreg[j] = Kg[tid + j * NT];
      const float* Vg = Vb + (size_t)(k0 + TK) * kD;
#pragma unroll
      for (int j = 0; j < 4; ++j)
#pragma unroll
        for (int t = 0; t < 4; ++t)
          vreg[4 * j + t] = Vg[(size_t)(vt0 + 16 * j + t) * kD + vd];
    }
    __syncthreads();

    // ---- QK^T: 16x16 warp tile, k=128 -> 8 m16n8k16 steps ----
    float sacc[2][4];
#pragma unroll
    for (int j = 0; j < 2; ++j)
#pragma unroll
      for (int v = 0; v < 4; ++v) sacc[j][v] = 0.f;
#pragma unroll
    for (int s = 0; s < 8; ++s) {
      uint32_t a[4], bk[4];
      ldm_x4(a, qa + (uint32_t)(s * 32));
      ldm_x4(bk, kb + (uint32_t)(s * 32));
      mma_f16(sacc[0], a, bk[0], bk[1]);
      mma_f16(sacc[1], a, bk[2], bk[3]);
    }

    // ---- mask + exp (hybrid); attn store; Ps store (fp16); Z partials ----
    const bool diag = (kt == qt);
    float rs0 = 0.f, rs1 = 0.f;
    float* arow0 = attnb + (size_t)(q0 + r0) * kS + k0;
    float* arow1 = attnb + (size_t)(q0 + r1) * kS + k0;
#pragma unroll
    for (int j = 0; j < 2; ++j) {
      const int c = 16 * wc + 8 * j + 2 * tig;
      float x00 = exp_mufu(sacc[j][0]);
      float x01 = exp_mufu(sacc[j][1]);
      float x10 = (j == 1) ? exp_poly(sacc[j][2]) : exp_mufu(sacc[j][2]);
      float x11 = (j == 1) ? exp_poly(sacc[j][3]) : exp_mufu(sacc[j][3]);
      float e00, e01, e10, e11;
      if (diag) {
        e00 = (c     > r0) ? x00 : 1.0f;
        e01 = (c + 1 > r0) ? x01 : 1.0f;
        e10 = (c     > r1) ? x10 : 1.0f;
        e11 = (c + 1 > r1) ? x11 : 1.0f;
      } else {
        e00 = x00; e01 = x01; e10 = x10; e11 = x11;
      }
      rs0 += e00 + e01;
      rs1 += e10 + e11;
      *reinterpret_cast<float2*>(arow0 + c) = make_float2(e00, e01);
      *reinterpret_cast<float2*>(arow1 + c) = make_float2(e10, e11);
      *reinterpret_cast<uint32_t*>(smP + r0 * (PP * 2) + c * 2) = h2pack(e00, e01);
      *reinterpret_cast<uint32_t*>(smP + r1 * (PP * 2) + c * 2) = h2pack(e10, e11);
    }
    rs0 += __shfl_xor_sync(0xffffffffu, rs0, 1, 4);
    rs0 += __shfl_xor_sync(0xffffffffu, rs0, 2, 4);
    rs1 += __shfl_xor_sync(0xffffffffu, rs1, 1, 4);
    rs1 += __shfl_xor_sync(0xffffffffu, rs1, 2, 4);
    if (tig == 0) { sm.Zp[wc][r0] = rs0; sm.Zp[wc][r1] = rs1; }
    __syncthreads();
    if (tid < TQ)
      sm.Zs[tid] += (sm.Zp[0][tid] + sm.Zp[1][tid]) +
                    (sm.Zp[2][tid] + sm.Zp[3][tid]);

    // ---- PV: 16 rows x 32 d-cols per warp, k=64 -> 4 m16n8k16 steps ----
#pragma unroll
    for (int kk = 0; kk < 4; ++kk) {
      uint32_t ap[4], bv0[4], bv1[4];
      ldm_x4(ap, pa + (uint32_t)(kk * 32));
      ldm_x4(bv0, vb0 + (uint32_t)(kk * 32));
      ldm_x4(bv1, vb1 + (uint32_t)(kk * 32));
      mma_f16(oacc[0], ap, bv0[0], bv0[1]);
      mma_f16(oacc[1], ap, bv0[2], bv0[3]);
      mma_f16(oacc[2], ap, bv1[0], bv1[1]);
      mma_f16(oacc[3], ap, bv1[2], bv1[3]);
    }
  }

  // ================= Phase 2 =================
  __syncthreads();
  if (tid < TQ) sm.rZs[tid] = 1.0f / sm.Zs[tid];
  __syncthreads();

  // lower-region V column sums (deterministic, 4-way MLP)
  {
    const int vc = tid & 127, vq = tid >> 7;
    float a0 = 0.f, a1 = 0.f, a2 = 0.f, a3 = 0.f;
    for (int t = vq; t < q0; t += 16) {
      a0 += Vb[(size_t)t * kD + vc];
      a1 += Vb[(size_t)(t + 4) * kD + vc];
      a2 += Vb[(size_t)(t + 8) * kD + vc];
      a3 += Vb[(size_t)(t + 12) * kD + vc];
    }
    sm.Vps[vq][vc] = (a0 + a1) + (a2 + a3);
  }

  // lower attn fill = 1/Z
  const int ftr = tid >> 4, ftc = tid & 15;
  for (int kt = 0; kt < qt; ++kt) {
    const int k0 = kt * TK;
#pragma unroll
    for (int p = 0; p < 2; ++p) {
      const int r = ftr + 32 * p;
      const float rz = sm.rZs[r];
      *reinterpret_cast<float4*>(&attnb[(size_t)(q0 + r) * kS + k0 + 4 * ftc]) =
          make_float4(rz, rz, rz, rz);
    }
  }
  __syncthreads();
  if (tid < kD)
    sm.Vcsum[tid] = (sm.Vps[0][tid] + sm.Vps[1][tid]) +
                    (sm.Vps[2][tid] + sm.Vps[3][tid]);
  __syncthreads();

  // rescale upper attn tiles (2 k-tiles in flight)
  {
    const float rzA = sm.rZs[ftr];
    const float rzB = sm.rZs[ftr + 32];
    int kt = qt;
    for (; kt + 1 < NKT; kt += 2) {
      float4* p00 = reinterpret_cast<float4*>(&attnb[(size_t)(q0 + ftr) * kS + kt * TK + 4 * ftc]);
      float4* p01 = reinterpret_cast<float4*>(&attnb[(size_t)(q0 + ftr + 32) * kS + kt * TK + 4 * ftc]);
      float4* p10 = reinterpret_cast<float4*>(&attnb[(size_t)(q0 + ftr) * kS + (kt + 1) * TK + 4 * ftc]);
      float4* p11 = reinterpret_cast<float4*>(&attnb[(size_t)(q0 + ftr + 32) * kS + (kt + 1) * TK + 4 * ftc]);
      float4 v00 = *p00, v01 = *p01, v10 = *p10, v11 = *p11;
      v00.x *= rzA; v00.y *= rzA; v00.z *= rzA; v00.w *= rzA;
      v01.x *= rzB; v01.y *= rzB; v01.z *= rzB; v01.w *= rzB;
      v10.x *= rzA; v10.y *= rzA; v10.z *= rzA; v10.w *= rzA;
      v11.x *= rzB; v11.y *= rzB; v11.z *= rzB; v11.w *= rzB;
      *p00 = v00; *p01 = v01; *p10 = v10; *p11 = v11;
    }
    if (kt < NKT) {
      float4* p00 = reinterpret_cast<float4*>(&attnb[(size_t)(q0 + ftr) * kS + kt * TK + 4 * ftc]);
      float4* p01 = reinterpret_cast<float4*>(&attnb[(size_t)(q0 + ftr + 32) * kS + kt * TK + 4 * ftc]);
      float4 v00 = *p00, v01 = *p01;
      v00.x *= rzA; v00.y *= rzA; v00.z *= rzA; v00.w *= rzA;
      v01.x *= rzB; v01.y *= rzB; v01.z *= rzB; v01.w *= rzB;
      *p00 = v00; *p01 = v01;
    }
  }

  // final output
  {
    const float rz0 = sm.rZs[r0], rz1 = sm.rZs[r1];
#pragma unroll
    for (int j = 0; j < 4; ++j) {
      const int c = 32 * wc + 8 * j + 2 * tig;
      const float vs0 = sm.Vcsum[c], vs1 = sm.Vcsum[c + 1];
      float2 o0 = make_float2(rz0 * (oacc[j][0] + vs0), rz0 * (oacc[j][1] + vs1));
      float2 o1 = make_float2(rz1 * (oacc[j][2] + vs0), rz1 * (oacc[j][3] + vs1));
      *reinterpret_cast<float2*>(&outb[(size_t)(q0 + r0) * kD + c]) = o0;
      *reinterpret_cast<float2*>(&outb[(size_t)(q0 + r1) * kD + c]) = o1;
    }
  }
}

extern "C" void kernel_launch(void* const* d_in, const int* in_sizes, int n_in,
                              void* d_out, int out_size) {
  (void)in_sizes; (void)n_in; (void)out_size;
  const float* Q = (const float*)d_in[0];
  const float* K = (const float*)d_in[1];
  const float* V = (const float*)d_in[2];
  float* out  = (float*)d_out;
  float* attn = out + (size_t)kB * kS * kD;

  cudaFuncSetAttribute(sdpa_kernel, cudaFuncAttributeMaxDynamicSharedMemorySize,
                       SMEM_BYTES);
  dim3 grid(NKT, kB);
  sdpa_kernel<<<grid, NT, SMEM_BYTES>>>(Q, K, V, out, attn);
}